// round 9
// baseline (speedup 1.0000x reference)
#include <cuda_runtime.h>
#include <cuda_bf16.h>
#include <mma.h>
#include <cstdint>
#include <math.h>

using namespace nvcuda;

#define Bb 256
#define Ll 256
#define Dd 768
#define Hh 1024
#define Tt 32
#define KV (3*Dd)   // 2304
#define Gg (4*Hh)   // 4096
#define NL (3*Ll)   // 768
#define KCH 64      // K elems per smem chunk
#define LDS 72      // padded smem stride (elems), 144 B

// GEMM tile config: 64x64 CTA tile
#define BMg 64
#define BNg 64
#define SSg ((2*BMg + 2*BNg) * LDS * 2)     // 36864 B per stage
#define AOFFg (BMg * LDS * 2)
#define BOFFg (2 * BMg * LDS * 2)
#define BLOFFg (BOFFg + BNg * LDS * 2)
#define SMEMg (2 * SSg)                      // 73728

// ======================= device scratch =======================
__device__ float g_c[Bb*Hh];
__device__ float g_att0[Bb*NL];           // logits partial, K half 0
__device__ float g_att1[Bb*NL];           // logits partial, K half 1
__device__ float g_gates[Bb*Gg];          // hh partial, gate-interleaved cols
__device__ float g_biasG[Gg];             // reordered: [unit*4+gate]
__device__ float g_biasA[NL];
__device__ __align__(16) __nv_bfloat16 g_hh_[Bb*Hh], g_hl_[Bb*Hh];
__device__ __align__(16) __nv_bfloat16 g_vh_[Bb*KV], g_vl_[Bb*KV];
__device__ __align__(16) __nv_bfloat16 g_Wah[NL*Hh],  g_Wal[NL*Hh];
__device__ __align__(16) __nv_bfloat16 g_Wihh[Gg*KV], g_Wihl[Gg*KV];   // rows reordered
__device__ __align__(16) __nv_bfloat16 g_Whhh[Gg*Hh], g_Whhl[Gg*Hh];   // rows reordered

__device__ __forceinline__ void split2(float a, __nv_bfloat16* hi, __nv_bfloat16* lo) {
    __nv_bfloat16 h = __float2bfloat16_rn(a);
    *hi = h;
    *lo = __float2bfloat16_rn(a - __bfloat162float(h));
}
__device__ __forceinline__ uint32_t smem_u32(const void* p) {
    uint32_t a;
    asm("{ .reg .u64 t; cvta.to.shared.u64 t, %1; cvt.u32.u64 %0, t; }" : "=r"(a) : "l"(p));
    return a;
}
__device__ __forceinline__ void cp16(uint32_t s, const void* g) {
    asm volatile("cp.async.cg.shared.global [%0], [%1], 16;" :: "r"(s), "l"(g));
}
#define CP_COMMIT() asm volatile("cp.async.commit_group;" ::: "memory")
#define CP_WAIT(n)  asm volatile("cp.async.wait_group %0;" :: "n"(n) : "memory")
__device__ __forceinline__ float sigmoidf_(float x) { return 1.0f / (1.0f + expf(-x)); }

// ======================= prep kernels =======================
__global__ void split_kernel(const float* __restrict__ src, __nv_bfloat16* __restrict__ hi,
                             __nv_bfloat16* __restrict__ lo, int n) {
    for (int i = blockIdx.x * blockDim.x + threadIdx.x; i < n; i += gridDim.x * blockDim.x)
        split2(src[i], &hi[i], &lo[i]);
}

// split + gate-interleave row reorder: orig row r = gate*1024+unit -> r' = unit*4+gate
__global__ void split_reorder_kernel(const float* __restrict__ src, __nv_bfloat16* __restrict__ hi,
                                     __nv_bfloat16* __restrict__ lo, int K, int n) {
    for (int i = blockIdx.x * blockDim.x + threadIdx.x; i < n; i += gridDim.x * blockDim.x) {
        int r = i / K, k = i - r * K;
        int gate = r >> 10, unit = r & 1023;
        size_t dst = (size_t)(unit * 4 + gate) * K + k;
        split2(src[i], &hi[dst], &lo[dst]);
    }
}

__global__ void bias_prep_kernel(const float* __restrict__ b_ih, const float* __restrict__ b_hh,
                                 const float* __restrict__ b1, const float* __restrict__ b2,
                                 const float* __restrict__ b3) {
    int j = blockIdx.x * blockDim.x + threadIdx.x;
    if (j < Gg) {
        int gate = j >> 10, unit = j & 1023;
        g_biasG[unit * 4 + gate] = b_ih[j] + b_hh[j];
    }
    if (j < NL) g_biasA[j] = (j < Ll) ? b1[j] : (j < 2*Ll) ? b2[j - Ll] : b3[j - 2*Ll];
}

__global__ void init_kernel(const float* __restrict__ h0, const float* __restrict__ c0) {
    int i = blockIdx.x * blockDim.x + threadIdx.x;
    if (i < Bb*Hh) { split2(h0[i], &g_hh_[i], &g_hl_[i]); g_c[i] = c0[i]; }
}

// ======================= GEMM mainloop core (64x64 tile, 128 thr, warps 2x2) ============
template <int NCH>
__device__ __forceinline__ void gemm_core(
    char* smem, uint32_t sb, int tid,
    const __nv_bfloat16* __restrict__ Ah, const __nv_bfloat16* __restrict__ Al,
    const __nv_bfloat16* __restrict__ Wh, const __nv_bfloat16* __restrict__ Wl,
    int K, int row0, int col0,
    wmma::fragment<wmma::accumulator, 16, 16, 16, float> (&acc)[2][2],
    int wm, int wn)
{
    auto load_chunk = [&](int kc, int s) {
        const int ka = kc * KCH;
        const uint32_t st = sb + s * SSg;
        #pragma unroll
        for (int it = 0; it < 4; it++) {
            int idx = tid + it * 128, r = idx >> 3, q = idx & 7;
            size_t src = (size_t)(row0 + r) * K + ka + q * 8;
            uint32_t off = r * (LDS*2) + q * 16;
            cp16(st + off, Ah + src);
            cp16(st + AOFFg + off, Al + src);
        }
        #pragma unroll
        for (int it = 0; it < 4; it++) {
            int idx = tid + it * 128, r = idx >> 3, q = idx & 7;
            size_t src = (size_t)(col0 + r) * K + ka + q * 8;
            uint32_t off = r * (LDS*2) + q * 16;
            cp16(st + BOFFg + off, Wh + src);
            cp16(st + BLOFFg + off, Wl + src);
        }
    };

    load_chunk(0, 0); CP_COMMIT();
    for (int kc = 0; kc < NCH; kc++) {
        if (kc + 1 < NCH) { load_chunk(kc + 1, (kc + 1) & 1); CP_COMMIT(); CP_WAIT(1); }
        else              { CP_WAIT(0); }
        __syncthreads();
        const char* st = smem + (kc & 1) * SSg;
        const __nv_bfloat16* pAh = (const __nv_bfloat16*)st;
        const __nv_bfloat16* pAl = (const __nv_bfloat16*)(st + AOFFg);
        const __nv_bfloat16* pBh = (const __nv_bfloat16*)(st + BOFFg);
        const __nv_bfloat16* pBl = (const __nv_bfloat16*)(st + BLOFFg);
        #pragma unroll
        for (int k16 = 0; k16 < KCH/16; k16++) {
            const int kk = k16 * 16;
            wmma::fragment<wmma::matrix_a, 16, 16, 16, __nv_bfloat16, wmma::row_major> ah[2], al[2];
            wmma::fragment<wmma::matrix_b, 16, 16, 16, __nv_bfloat16, wmma::col_major> bh[2], bl[2];
            #pragma unroll
            for (int i = 0; i < 2; i++) {
                int rr = wm * 32 + i * 16;
                wmma::load_matrix_sync(ah[i], pAh + rr * LDS + kk, LDS);
                wmma::load_matrix_sync(al[i], pAl + rr * LDS + kk, LDS);
            }
            #pragma unroll
            for (int j = 0; j < 2; j++) {
                int cc = wn * 32 + j * 16;
                wmma::load_matrix_sync(bh[j], pBh + cc * LDS + kk, LDS);
                wmma::load_matrix_sync(bl[j], pBl + cc * LDS + kk, LDS);
            }
            #pragma unroll
            for (int i = 0; i < 2; i++)
                #pragma unroll
                for (int j = 0; j < 2; j++) {
                    wmma::mma_sync(acc[i][j], ah[i], bh[j], acc[i][j]);
                    wmma::mma_sync(acc[i][j], ah[i], bl[j], acc[i][j]);
                    wmma::mma_sync(acc[i][j], al[i], bh[j], acc[i][j]);
                }
        }
        __syncthreads();
    }
}

// ======================= logits, split-K 2-way =======================
// 96 CTAs x 128 thr: bid<48 -> K half 0 -> g_att0; else half 1 -> g_att1.
__global__ void __launch_bounds__(128) logits_kernel() {
    extern __shared__ __align__(16) char smem[];
    const uint32_t sb = smem_u32(smem);
    const int tid = threadIdx.x, wid = tid >> 5, wm = wid >> 1, wn = wid & 1;
    const int bid = blockIdx.x;
    const int half = bid < 48 ? 0 : 1;
    const int tile = half ? bid - 48 : bid;
    const int m_t = tile & 3, n_t = tile >> 2;          // n_t 0..11
    const int row0 = m_t * BMg, col0 = n_t * BNg;
    float* C = half ? g_att1 : g_att0;
    const int ko = half * 512;

    wmma::fragment<wmma::accumulator, 16, 16, 16, float> acc[2][2];
    #pragma unroll
    for (int i = 0; i < 2; i++) for (int j = 0; j < 2; j++) wmma::fill_fragment(acc[i][j], 0.0f);

    gemm_core<8>(smem, sb, tid, g_hh_ + ko, g_hl_ + ko, g_Wah + ko, g_Wal + ko,
                 Hh, row0, col0, acc, wm, wn);

    #pragma unroll
    for (int i = 0; i < 2; i++)
        #pragma unroll
        for (int j = 0; j < 2; j++) {
            int row = row0 + wm * 32 + i * 16;
            int col = col0 + wn * 32 + j * 16;
            wmma::store_matrix_sync(&C[(size_t)row * NL + col], acc[i][j], NL, wmma::mem_row_major);
        }
}

// ======================= fusedB: attnv (even bid) + gates_hh (odd bid) =======================
// 512 CTAs x 256 thr. attnv: softmax(att0+att1+bias) then value gather over x.
// hh: 64x64 tile of (h_h+h_l)@(Whh_h+Whh_l)^T -> g_gates, 8 warps (4x2), warp tile 16x32.
__global__ void __launch_bounds__(256) fusedB_kernel(const float* __restrict__ x) {
    extern __shared__ __align__(16) char smem[];
    const int tid = threadIdx.x;
    const int bid = blockIdx.x;

    if (bid & 1) {
        // ---------------- gates_hh tile ----------------
        const uint32_t sb = smem_u32(smem);
        const int tile = bid >> 1;                       // 0..255
        const int m_t = tile & 3, n_t = tile >> 2;       // n_t 0..63
        const int row0 = m_t * BMg, col0 = n_t * BNg;
        const int wid = tid >> 5;
        const int wm = wid >> 1, wn = wid & 1;           // wm 0..3 (16 rows), wn 0..1 (32 cols)

        wmma::fragment<wmma::accumulator, 16, 16, 16, float> acc[2];
        #pragma unroll
        for (int j = 0; j < 2; j++) wmma::fill_fragment(acc[j], 0.0f);

        auto load_chunk = [&](int kc, int s) {
            const int ka = kc * KCH;
            const uint32_t st = sb + s * SSg;
            #pragma unroll
            for (int it = 0; it < 2; it++) {
                int idx = tid + it * 256, r = idx >> 3, q = idx & 7;
                size_t src = (size_t)(row0 + r) * Hh + ka + q * 8;
                uint32_t off = r * (LDS*2) + q * 16;
                cp16(st + off, g_hh_ + src);
                cp16(st + AOFFg + off, g_hl_ + src);
            }
            #pragma unroll
            for (int it = 0; it < 2; it++) {
                int idx = tid + it * 256, r = idx >> 3, q = idx & 7;
                size_t src = (size_t)(col0 + r) * Hh + ka + q * 8;
                uint32_t off = r * (LDS*2) + q * 16;
                cp16(st + BOFFg + off, g_Whhh + src);
                cp16(st + BLOFFg + off, g_Whhl + src);
            }
        };

        load_chunk(0, 0); CP_COMMIT();
        for (int kc = 0; kc < Hh/KCH; kc++) {
            if (kc + 1 < Hh/KCH) { load_chunk(kc + 1, (kc + 1) & 1); CP_COMMIT(); CP_WAIT(1); }
            else                 { CP_WAIT(0); }
            __syncthreads();
            const char* st = smem + (kc & 1) * SSg;
            const __nv_bfloat16* pAh = (const __nv_bfloat16*)st;
            const __nv_bfloat16* pAl = (const __nv_bfloat16*)(st + AOFFg);
            const __nv_bfloat16* pBh = (const __nv_bfloat16*)(st + BOFFg);
            const __nv_bfloat16* pBl = (const __nv_bfloat16*)(st + BLOFFg);
            #pragma unroll
            for (int k16 = 0; k16 < KCH/16; k16++) {
                const int kk = k16 * 16;
                wmma::fragment<wmma::matrix_a, 16, 16, 16, __nv_bfloat16, wmma::row_major> ah, al;
                wmma::fragment<wmma::matrix_b, 16, 16, 16, __nv_bfloat16, wmma::col_major> bh[2], bl[2];
                int rr = wm * 16;
                wmma::load_matrix_sync(ah, pAh + rr * LDS + kk, LDS);
                wmma::load_matrix_sync(al, pAl + rr * LDS + kk, LDS);
                #pragma unroll
                for (int j = 0; j < 2; j++) {
                    int cc = wn * 32 + j * 16;
                    wmma::load_matrix_sync(bh[j], pBh + cc * LDS + kk, LDS);
                    wmma::load_matrix_sync(bl[j], pBl + cc * LDS + kk, LDS);
                }
                #pragma unroll
                for (int j = 0; j < 2; j++) {
                    wmma::mma_sync(acc[j], ah, bh[j], acc[j]);
                    wmma::mma_sync(acc[j], ah, bl[j], acc[j]);
                    wmma::mma_sync(acc[j], al, bh[j], acc[j]);
                }
            }
            __syncthreads();
        }
        #pragma unroll
        for (int j = 0; j < 2; j++) {
            int row = row0 + wm * 16;
            int col = col0 + wn * 32 + j * 16;
            wmma::store_matrix_sync(&g_gates[(size_t)row * Gg + col], acc[j], Gg, wmma::mem_row_major);
        }
    } else {
        // ---------------- attnv for batch b ----------------
        const int b = bid >> 1;
        float*  a    = (float*)smem;                     // [3*256]
        float2* part = (float2*)(smem + 3072);           // [3][2][384]
        float*  red  = (float*)(smem + 3072 + 18432);    // [3][8]

        // softmax: thread tid owns column tid for all 3 heads
        {
            float v[3], e[3];
            #pragma unroll
            for (int h = 0; h < 3; h++)
                v[h] = g_att0[b * NL + h * 256 + tid] + g_att1[b * NL + h * 256 + tid]
                     + g_biasA[h * 256 + tid];
            int w8 = tid >> 5;
            #pragma unroll
            for (int h = 0; h < 3; h++) {
                float m = v[h];
                #pragma unroll
                for (int o = 16; o; o >>= 1) m = fmaxf(m, __shfl_xor_sync(0xffffffffu, m, o));
                if ((tid & 31) == 0) red[h * 8 + w8] = m;
            }
            __syncthreads();
            float mm[3];
            #pragma unroll
            for (int h = 0; h < 3; h++) {
                float m = red[h * 8];
                #pragma unroll
                for (int q = 1; q < 8; q++) m = fmaxf(m, red[h * 8 + q]);
                mm[h] = m;
            }
            __syncthreads();
            #pragma unroll
            for (int h = 0; h < 3; h++) {
                e[h] = expf(v[h] - mm[h]);
                float s = e[h];
                #pragma unroll
                for (int o = 16; o; o >>= 1) s += __shfl_xor_sync(0xffffffffu, s, o);
                if ((tid & 31) == 0) red[h * 8 + w8] = s;
            }
            __syncthreads();
            #pragma unroll
            for (int h = 0; h < 3; h++) {
                float s = red[h * 8];
                #pragma unroll
                for (int q = 1; q < 8; q++) s += red[h * 8 + q];
                a[h * 256 + tid] = e[h] / s;
            }
        }
        __syncthreads();

        // value gather: L split 2-way (ty), 384 float2 cols split over 128 threads x 3 groups
        const int ty = tid >> 7, tx = tid & 127;
        const float2* xb2 = (const float2*)(x + (size_t)b * Ll * Dd);
        float2 s0a={0,0}, s0b={0,0}, s0c={0,0};
        float2 s1a={0,0}, s1b={0,0}, s1c={0,0};
        float2 s2a={0,0}, s2b={0,0}, s2c={0,0};
        const int l0 = ty * 128;
        #pragma unroll 4
        for (int l = l0; l < l0 + 128; l++) {
            float w0 = a[l], w1 = a[256 + l], w2 = a[512 + l];
            const float2* rowp = xb2 + (size_t)l * 384;
            float2 xa = rowp[tx], xb = rowp[128 + tx], xc = rowp[256 + tx];
            s0a.x += w0*xa.x; s0a.y += w0*xa.y; s0b.x += w0*xb.x; s0b.y += w0*xb.y; s0c.x += w0*xc.x; s0c.y += w0*xc.y;
            s1a.x += w1*xa.x; s1a.y += w1*xa.y; s1b.x += w1*xb.x; s1b.y += w1*xb.y; s1c.x += w1*xc.x; s1c.y += w1*xc.y;
            s2a.x += w2*xa.x; s2a.y += w2*xa.y; s2b.x += w2*xb.x; s2b.y += w2*xb.y; s2c.x += w2*xc.x; s2c.y += w2*xc.y;
        }
        part[(0*2 + ty)*384 + 0*128 + tx] = s0a;
        part[(0*2 + ty)*384 + 1*128 + tx] = s0b;
        part[(0*2 + ty)*384 + 2*128 + tx] = s0c;
        part[(1*2 + ty)*384 + 0*128 + tx] = s1a;
        part[(1*2 + ty)*384 + 1*128 + tx] = s1b;
        part[(1*2 + ty)*384 + 2*128 + tx] = s1c;
        part[(2*2 + ty)*384 + 0*128 + tx] = s2a;
        part[(2*2 + ty)*384 + 1*128 + tx] = s2b;
        part[(2*2 + ty)*384 + 2*128 + tx] = s2c;
        __syncthreads();

        for (int sIdx = tid; sIdx < 1152; sIdx += 256) {
            int h = sIdx / 384, rem = sIdx % 384;
            float2 r0 = part[(h*2 + 0)*384 + rem];
            float2 r1 = part[(h*2 + 1)*384 + rem];
            float rx = r0.x + r1.x, ry = r0.y + r1.y;
            size_t o = (size_t)b * KV + h * Dd + rem * 2;
            split2(rx, &g_vh_[o],     &g_vl_[o]);
            split2(ry, &g_vh_[o + 1], &g_vl_[o + 1]);
        }
    }
}

// ======================= gates_ih + fused LSTM (A=v, K=2304) =======================
__global__ void __launch_bounds__(128) gates_ih_kernel(float* __restrict__ out, int t_step) {
    extern __shared__ __align__(16) char smem[];
    const uint32_t sb = smem_u32(smem);
    const int tid = threadIdx.x, wid = tid >> 5, wm = wid >> 1, wn = wid & 1;
    const int bid = blockIdx.x;                 // 256 CTAs
    const int m_t = bid & 3, n_t = bid >> 2;    // n_t 0..63
    const int row0 = m_t * BMg, col0 = n_t * BNg;

    wmma::fragment<wmma::accumulator, 16, 16, 16, float> acc[2][2];
    #pragma unroll
    for (int i = 0; i < 2; i++) for (int j = 0; j < 2; j++) wmma::fill_fragment(acc[i][j], 0.0f);

    gemm_core<KV/KCH>(smem, sb, tid, g_vh_, g_vl_, g_Wihh, g_Wihl, KV, row0, col0, acc, wm, wn);

    // stage acc tile (64 x 64, stride 68) then fused LSTM epilogue
    float* smf = (float*)smem;
    #pragma unroll
    for (int i = 0; i < 2; i++)
        #pragma unroll
        for (int j = 0; j < 2; j++)
            wmma::store_matrix_sync(smf + (wm*32 + i*16) * 68 + (wn*32 + j*16),
                                    acc[i][j], 68, wmma::mem_row_major);
    __syncthreads();

    const int unit0 = n_t * 16;                 // 16 hidden units per CTA (4 gates each)
    #pragma unroll
    for (int it = 0; it < 8; it++) {
        int idx = tid + it * 128;               // 0..1023
        int r = idx >> 4, u = idx & 15;
        int row = row0 + r, j = unit0 + u;
        float4 av = *(const float4*)&smf[r * 68 + u * 4];
        float4 pv = *(const float4*)&g_gates[(size_t)row * Gg + n_t * 64 + u * 4];
        float4 bv = *(const float4*)&g_biasG[n_t * 64 + u * 4];
        float ig = av.x + pv.x + bv.x;
        float fg = av.y + pv.y + bv.y;
        float gg = av.z + pv.z + bv.z;
        float og = av.w + pv.w + bv.w;
        int ci = row * Hh + j;
        float c = g_c[ci];
        float cn = sigmoidf_(fg) * c + sigmoidf_(ig) * tanhf(gg);
        float hn = sigmoidf_(og) * tanhf(cn);
        g_c[ci] = cn;
        split2(hn, &g_hh_[ci], &g_hl_[ci]);
        out[((size_t)row * Tt + t_step) * Hh + j] = hn;
    }
}

// ======================= driver (single stream, graph-safe) =======================
extern "C" void kernel_launch(void* const* d_in, const int* in_sizes, int n_in,
                              void* d_out, int out_size) {
    (void)in_sizes; (void)n_in; (void)out_size;
    const float* x    = (const float*)d_in[0];
    const float* h0   = (const float*)d_in[1];
    const float* c0   = (const float*)d_in[2];
    const float* W1   = (const float*)d_in[3];
    const float* b1   = (const float*)d_in[4];
    const float* W2   = (const float*)d_in[5];
    const float* b2   = (const float*)d_in[6];
    const float* W3   = (const float*)d_in[7];
    const float* b3   = (const float*)d_in[8];
    const float* W_ih = (const float*)d_in[9];
    const float* W_hh = (const float*)d_in[10];
    const float* b_ih = (const float*)d_in[11];
    const float* b_hh = (const float*)d_in[12];
    float* out = (float*)d_out;

    cudaFuncSetAttribute(logits_kernel,   cudaFuncAttributeMaxDynamicSharedMemorySize, SMEMg);
    cudaFuncSetAttribute(fusedB_kernel,   cudaFuncAttributeMaxDynamicSharedMemorySize, SMEMg);
    cudaFuncSetAttribute(gates_ih_kernel, cudaFuncAttributeMaxDynamicSharedMemorySize, SMEMg);

    __nv_bfloat16 *wah, *wal, *wihh, *wihl, *whhh, *whhl;
    cudaGetSymbolAddress((void**)&wah,  g_Wah);
    cudaGetSymbolAddress((void**)&wal,  g_Wal);
    cudaGetSymbolAddress((void**)&wihh, g_Wihh);
    cudaGetSymbolAddress((void**)&wihl, g_Wihl);
    cudaGetSymbolAddress((void**)&whhh, g_Whhh);
    cudaGetSymbolAddress((void**)&whhl, g_Whhl);

    split_reorder_kernel<<<4096, 256>>>(W_ih, wihh, wihl, KV, Gg*KV);
    split_reorder_kernel<<<4096, 256>>>(W_hh, whhh, whhl, Hh, Gg*Hh);
    split_kernel<<<1024, 256>>>(W1, wah,           wal,           Ll*Hh);
    split_kernel<<<1024, 256>>>(W2, wah + Ll*Hh,   wal + Ll*Hh,   Ll*Hh);
    split_kernel<<<1024, 256>>>(W3, wah + 2*Ll*Hh, wal + 2*Ll*Hh, Ll*Hh);
    bias_prep_kernel<<<16, 256>>>(b_ih, b_hh, b1, b2, b3);
    init_kernel<<<(Bb*Hh + 255)/256, 256>>>(h0, c0);

    for (int t = 0; t < Tt; t++) {
        logits_kernel<<<96, 128, SMEMg>>>();               // split-K logits partials
        fusedB_kernel<<<512, 256, SMEMg>>>(x);             // attnv (softmax+value) || gates_hh
        gates_ih_kernel<<<256, 128, SMEMg>>>(out, t);      // ih GEMM + LSTM epilogue
    }
}

// round 10
// speedup vs baseline: 1.1371x; 1.1371x over previous
#include <cuda_runtime.h>
#include <cuda_bf16.h>
#include <mma.h>
#include <cstdint>
#include <math.h>

using namespace nvcuda;

#define Bb 256
#define Ll 256
#define Dd 768
#define Hh 1024
#define Tt 32
#define KV (3*Dd)   // 2304
#define Gg (4*Hh)   // 4096
#define NL (3*Ll)   // 768
#define KCH 64      // K elems per smem chunk
#define LDS 72      // padded smem stride (elems), 144 B

// GEMM tile: 64x128 CTA, 128 threads (4 warps 2x2), warp tile 32x64 (FM=2, FN=4)
#define BMg 64
#define BNg 128
#define SSg ((2*BMg + 2*BNg) * LDS * 2)     // 55296 B per stage
#define AOFFg (BMg * LDS * 2)                // 9216
#define BOFFg (2 * BMg * LDS * 2)            // 18432
#define BLOFFg (BOFFg + BNg * LDS * 2)       // 36864
#define SMEMg (2 * SSg)                      // 110592

// ======================= device scratch =======================
__device__ float g_c[Bb*Hh];
__device__ float g_att[Bb*NL];
__device__ float g_gates[Bb*Gg];          // hh partial, gate-interleaved cols
__device__ float g_biasG[Gg];             // reordered: [unit*4+gate]
__device__ float g_biasA[NL];
__device__ __align__(16) __nv_bfloat16 g_hh_[Bb*Hh], g_hl_[Bb*Hh];
__device__ __align__(16) __nv_bfloat16 g_vh_[Bb*KV], g_vl_[Bb*KV];
__device__ __align__(16) __nv_bfloat16 g_Wah[NL*Hh],  g_Wal[NL*Hh];
__device__ __align__(16) __nv_bfloat16 g_Wihh[Gg*KV], g_Wihl[Gg*KV];   // rows reordered
__device__ __align__(16) __nv_bfloat16 g_Whhh[Gg*Hh], g_Whhl[Gg*Hh];   // rows reordered

__device__ __forceinline__ void split2(float a, __nv_bfloat16* hi, __nv_bfloat16* lo) {
    __nv_bfloat16 h = __float2bfloat16_rn(a);
    *hi = h;
    *lo = __float2bfloat16_rn(a - __bfloat162float(h));
}
__device__ __forceinline__ uint32_t smem_u32(const void* p) {
    uint32_t a;
    asm("{ .reg .u64 t; cvta.to.shared.u64 t, %1; cvt.u32.u64 %0, t; }" : "=r"(a) : "l"(p));
    return a;
}
__device__ __forceinline__ void cp16(uint32_t s, const void* g) {
    asm volatile("cp.async.cg.shared.global [%0], [%1], 16;" :: "r"(s), "l"(g));
}
#define CP_COMMIT() asm volatile("cp.async.commit_group;" ::: "memory")
#define CP_WAIT(n)  asm volatile("cp.async.wait_group %0;" :: "n"(n) : "memory")
__device__ __forceinline__ float sigmoidf_(float x) { return 1.0f / (1.0f + expf(-x)); }

// ======================= prep kernels =======================
__global__ void split_kernel(const float* __restrict__ src, __nv_bfloat16* __restrict__ hi,
                             __nv_bfloat16* __restrict__ lo, int n) {
    for (int i = blockIdx.x * blockDim.x + threadIdx.x; i < n; i += gridDim.x * blockDim.x)
        split2(src[i], &hi[i], &lo[i]);
}

// split + gate-interleave row reorder: orig row r = gate*1024+unit -> r' = unit*4+gate
__global__ void split_reorder_kernel(const float* __restrict__ src, __nv_bfloat16* __restrict__ hi,
                                     __nv_bfloat16* __restrict__ lo, int K, int n) {
    for (int i = blockIdx.x * blockDim.x + threadIdx.x; i < n; i += gridDim.x * blockDim.x) {
        int r = i / K, k = i - r * K;
        int gate = r >> 10, unit = r & 1023;
        size_t dst = (size_t)(unit * 4 + gate) * K + k;
        split2(src[i], &hi[dst], &lo[dst]);
    }
}

__global__ void bias_prep_kernel(const float* __restrict__ b_ih, const float* __restrict__ b_hh,
                                 const float* __restrict__ b1, const float* __restrict__ b2,
                                 const float* __restrict__ b3) {
    int j = blockIdx.x * blockDim.x + threadIdx.x;
    if (j < Gg) {
        int gate = j >> 10, unit = j & 1023;
        g_biasG[unit * 4 + gate] = b_ih[j] + b_hh[j];
    }
    if (j < NL) g_biasA[j] = (j < Ll) ? b1[j] : (j < 2*Ll) ? b2[j - Ll] : b3[j - 2*Ll];
}

__global__ void init_kernel(const float* __restrict__ h0, const float* __restrict__ c0) {
    int i = blockIdx.x * blockDim.x + threadIdx.x;
    if (i < Bb*Hh) { split2(h0[i], &g_hh_[i], &g_hl_[i]); g_c[i] = c0[i]; }
}

// ======================= GEMM mainloop core (64x128 tile, 128 thr, warps 2x2) ===========
// acc[2][4] = (Ah+Al)[row0:+64, :K] @ (Wh+Wl)[col0:+128, :K]^T  (3-term split)
template <int NCH>
__device__ __forceinline__ void gemm_core(
    char* smem, uint32_t sb, int tid,
    const __nv_bfloat16* __restrict__ Ah, const __nv_bfloat16* __restrict__ Al,
    const __nv_bfloat16* __restrict__ Wh, const __nv_bfloat16* __restrict__ Wl,
    int K, int row0, int col0,
    wmma::fragment<wmma::accumulator, 16, 16, 16, float> (&acc)[2][4],
    int wm, int wn)
{
    auto load_chunk = [&](int kc, int s) {
        const int ka = kc * KCH;
        const uint32_t st = sb + s * SSg;
        #pragma unroll
        for (int it = 0; it < 4; it++) {                 // A: 64 rows
            int idx = tid + it * 128, r = idx >> 3, q = idx & 7;
            size_t src = (size_t)(row0 + r) * K + ka + q * 8;
            uint32_t off = r * (LDS*2) + q * 16;
            cp16(st + off, Ah + src);
            cp16(st + AOFFg + off, Al + src);
        }
        #pragma unroll
        for (int it = 0; it < 8; it++) {                 // B: 128 rows
            int idx = tid + it * 128, r = idx >> 3, q = idx & 7;
            size_t src = (size_t)(col0 + r) * K + ka + q * 8;
            uint32_t off = r * (LDS*2) + q * 16;
            cp16(st + BOFFg + off, Wh + src);
            cp16(st + BLOFFg + off, Wl + src);
        }
    };

    load_chunk(0, 0); CP_COMMIT();
    for (int kc = 0; kc < NCH; kc++) {
        if (kc + 1 < NCH) { load_chunk(kc + 1, (kc + 1) & 1); CP_COMMIT(); CP_WAIT(1); }
        else              { CP_WAIT(0); }
        __syncthreads();
        const char* st = smem + (kc & 1) * SSg;
        const __nv_bfloat16* pAh = (const __nv_bfloat16*)st;
        const __nv_bfloat16* pAl = (const __nv_bfloat16*)(st + AOFFg);
        const __nv_bfloat16* pBh = (const __nv_bfloat16*)(st + BOFFg);
        const __nv_bfloat16* pBl = (const __nv_bfloat16*)(st + BLOFFg);
        #pragma unroll
        for (int k16 = 0; k16 < KCH/16; k16++) {
            const int kk = k16 * 16;
            wmma::fragment<wmma::matrix_a, 16, 16, 16, __nv_bfloat16, wmma::row_major> ah[2], al[2];
            #pragma unroll
            for (int i = 0; i < 2; i++) {
                int rr = wm * 32 + i * 16;
                wmma::load_matrix_sync(ah[i], pAh + rr * LDS + kk, LDS);
                wmma::load_matrix_sync(al[i], pAl + rr * LDS + kk, LDS);
            }
            #pragma unroll
            for (int j = 0; j < 4; j++) {
                int cc = wn * 64 + j * 16;
                wmma::fragment<wmma::matrix_b, 16, 16, 16, __nv_bfloat16, wmma::col_major> bh, bl;
                wmma::load_matrix_sync(bh, pBh + cc * LDS + kk, LDS);
                wmma::load_matrix_sync(bl, pBl + cc * LDS + kk, LDS);
                #pragma unroll
                for (int i = 0; i < 2; i++) {
                    wmma::mma_sync(acc[i][j], ah[i], bh, acc[i][j]);
                    wmma::mma_sync(acc[i][j], ah[i], bl, acc[i][j]);
                    wmma::mma_sync(acc[i][j], al[i], bh, acc[i][j]);
                }
            }
        }
        __syncthreads();
    }
}

// ======================= fused launch A: logits + gates_hh (both A=h, K=1024) ==========
// 152 CTAs x 128 thr: bid<24 -> logits tile (4x6), else gates_hh tile (4x32).
__global__ void __launch_bounds__(128) fusedA_kernel() {
    extern __shared__ __align__(16) char smem[];
    const uint32_t sb = smem_u32(smem);
    const int tid = threadIdx.x, wid = tid >> 5, wm = wid >> 1, wn = wid & 1;
    const int bid = blockIdx.x;

    const bool isLog = bid < 24;
    int m_t, n_t;
    const __nv_bfloat16 *Wh, *Wl;
    float* C;
    int Nt;
    if (isLog) {
        m_t = bid & 3; n_t = bid >> 2;          // 0..5
        Wh = g_Wah; Wl = g_Wal; C = g_att; Nt = NL;
    } else {
        int b2 = bid - 24;
        m_t = b2 & 3; n_t = b2 >> 2;            // 0..31
        Wh = g_Whhh; Wl = g_Whhl; C = g_gates; Nt = Gg;
    }
    const int row0 = m_t * BMg, col0 = n_t * BNg;

    wmma::fragment<wmma::accumulator, 16, 16, 16, float> acc[2][4];
    #pragma unroll
    for (int i = 0; i < 2; i++) for (int j = 0; j < 4; j++) wmma::fill_fragment(acc[i][j], 0.0f);

    gemm_core<Hh/KCH>(smem, sb, tid, g_hh_, g_hl_, Wh, Wl, Hh, row0, col0, acc, wm, wn);

    #pragma unroll
    for (int i = 0; i < 2; i++)
        #pragma unroll
        for (int j = 0; j < 4; j++) {
            int row = row0 + wm * 32 + i * 16;
            int col = col0 + wn * 64 + j * 16;
            wmma::store_matrix_sync(&C[(size_t)row * Nt + col], acc[i][j], Nt, wmma::mem_row_major);
        }
}

// ======================= gates_ih + fused LSTM (A=v, K=2304) =======================
// 128 CTAs x 128 thr, tile 64x128 (32 hidden units per CTA).
__global__ void __launch_bounds__(128) gates_ih_kernel(float* __restrict__ out, int t_step) {
    extern __shared__ __align__(16) char smem[];
    const uint32_t sb = smem_u32(smem);
    const int tid = threadIdx.x, wid = tid >> 5, wm = wid >> 1, wn = wid & 1;
    const int bid = blockIdx.x;                 // 128 CTAs
    const int m_t = bid & 3, n_t = bid >> 2;    // n_t 0..31
    const int row0 = m_t * BMg, col0 = n_t * BNg;

    wmma::fragment<wmma::accumulator, 16, 16, 16, float> acc[2][4];
    #pragma unroll
    for (int i = 0; i < 2; i++) for (int j = 0; j < 4; j++) wmma::fill_fragment(acc[i][j], 0.0f);

    gemm_core<KV/KCH>(smem, sb, tid, g_vh_, g_vl_, g_Wihh, g_Wihl, KV, row0, col0, acc, wm, wn);

    // stage acc tile (64 x 128, stride 132) then fused LSTM epilogue
    float* smf = (float*)smem;
    #pragma unroll
    for (int i = 0; i < 2; i++)
        #pragma unroll
        for (int j = 0; j < 4; j++)
            wmma::store_matrix_sync(smf + (wm*32 + i*16) * 132 + (wn*64 + j*16),
                                    acc[i][j], 132, wmma::mem_row_major);
    __syncthreads();

    const int unit0 = n_t * 32;                 // 32 hidden units per CTA (4 gates each)
    #pragma unroll
    for (int it = 0; it < 16; it++) {
        int idx = tid + it * 128;               // 0..2047
        int r = idx >> 5, u = idx & 31;
        int row = row0 + r, j = unit0 + u;
        float4 av = *(const float4*)&smf[r * 132 + u * 4];
        float4 pv = *(const float4*)&g_gates[(size_t)row * Gg + n_t * 128 + u * 4];
        float4 bv = *(const float4*)&g_biasG[n_t * 128 + u * 4];
        float ig = av.x + pv.x + bv.x;
        float fg = av.y + pv.y + bv.y;
        float gg = av.z + pv.z + bv.z;
        float og = av.w + pv.w + bv.w;
        int ci = row * Hh + j;
        float c = g_c[ci];
        float cn = sigmoidf_(fg) * c + sigmoidf_(ig) * tanhf(gg);
        float hn = sigmoidf_(og) * tanhf(cn);
        g_c[ci] = cn;
        split2(hn, &g_hh_[ci], &g_hl_[ci]);
        out[((size_t)row * Tt + t_step) * Hh + j] = hn;
    }
}

// ======================= fused softmax + attention-value, D-split 2-way =======================
// 512 CTAs x 384 thr: bid = b*2 + half. Each CTA handles D columns [half*384, +384).
__global__ void __launch_bounds__(384, 4) attnv_kernel(const float* __restrict__ x) {
    const int bid = blockIdx.x;
    const int b = bid >> 1, half = bid & 1;
    const int tid = threadIdx.x;

    __shared__ float a[3][Ll];
    __shared__ float2 part[3][2][192];
    __shared__ float red[3][8];

    // --- softmax (threads 0..255; full warps) ---
    float e[3], v[3];
    if (tid < 256) {
        #pragma unroll
        for (int h = 0; h < 3; h++)
            v[h] = g_att[b * NL + h * 256 + tid] + g_biasA[h * 256 + tid];
        int w8 = tid >> 5;
        #pragma unroll
        for (int h = 0; h < 3; h++) {
            float m = v[h];
            #pragma unroll
            for (int o = 16; o; o >>= 1) m = fmaxf(m, __shfl_xor_sync(0xffffffffu, m, o));
            if ((tid & 31) == 0) red[h][w8] = m;
        }
    }
    __syncthreads();
    if (tid < 256) {
        int w8 = tid >> 5;
        #pragma unroll
        for (int h = 0; h < 3; h++) {
            float mm = red[h][0];
            #pragma unroll
            for (int q = 1; q < 8; q++) mm = fmaxf(mm, red[h][q]);
            e[h] = expf(v[h] - mm);
        }
        __syncthreads();
        #pragma unroll
        for (int h = 0; h < 3; h++) {
            float s = e[h];
            #pragma unroll
            for (int o = 16; o; o >>= 1) s += __shfl_xor_sync(0xffffffffu, s, o);
            if ((tid & 31) == 0) red[h][w8] = s;
        }
    } else {
        __syncthreads();
    }
    __syncthreads();
    if (tid < 256) {
        #pragma unroll
        for (int h = 0; h < 3; h++) {
            float s = red[h][0];
            #pragma unroll
            for (int q = 1; q < 8; q++) s += red[h][q];
            a[h][tid] = e[h] / s;
        }
    }
    __syncthreads();

    // --- value gather over this CTA's D-half: 192 float2 cols, L split 2-way ---
    const int ty = tid / 192, tx = tid % 192;     // ty 0..1
    const float2* xb2 = (const float2*)(x + (size_t)b * Ll * Dd) + half * 192;
    float2 s0 = {0,0}, s1 = {0,0}, s2 = {0,0};
    const int l0 = ty * 128;
    #pragma unroll 8
    for (int l = l0; l < l0 + 128; l++) {
        float w0 = a[0][l], w1 = a[1][l], w2 = a[2][l];
        float2 xv = xb2[(size_t)l * 384 + tx];
        s0.x += w0*xv.x; s0.y += w0*xv.y;
        s1.x += w1*xv.x; s1.y += w1*xv.y;
        s2.x += w2*xv.x; s2.y += w2*xv.y;
    }
    part[0][ty][tx] = s0; part[1][ty][tx] = s1; part[2][ty][tx] = s2;
    __syncthreads();

    // reduce + split-write: 3 heads x 192 float2 = 576 items over 384 threads
    for (int sIdx = tid; sIdx < 576; sIdx += 384) {
        int h = sIdx / 192, c = sIdx % 192;
        float2 r0 = part[h][0][c], r1 = part[h][1][c];
        float rx = r0.x + r1.x, ry = r0.y + r1.y;
        size_t o = (size_t)b * KV + h * Dd + half * 384 + c * 2;
        split2(rx, &g_vh_[o],     &g_vl_[o]);
        split2(ry, &g_vh_[o + 1], &g_vl_[o + 1]);
    }
}

// ======================= driver (single stream, graph-safe) =======================
extern "C" void kernel_launch(void* const* d_in, const int* in_sizes, int n_in,
                              void* d_out, int out_size) {
    (void)in_sizes; (void)n_in; (void)out_size;
    const float* x    = (const float*)d_in[0];
    const float* h0   = (const float*)d_in[1];
    const float* c0   = (const float*)d_in[2];
    const float* W1   = (const float*)d_in[3];
    const float* b1   = (const float*)d_in[4];
    const float* W2   = (const float*)d_in[5];
    const float* b2   = (const float*)d_in[6];
    const float* W3   = (const float*)d_in[7];
    const float* b3   = (const float*)d_in[8];
    const float* W_ih = (const float*)d_in[9];
    const float* W_hh = (const float*)d_in[10];
    const float* b_ih = (const float*)d_in[11];
    const float* b_hh = (const float*)d_in[12];
    float* out = (float*)d_out;

    cudaFuncSetAttribute(fusedA_kernel,   cudaFuncAttributeMaxDynamicSharedMemorySize, SMEMg);
    cudaFuncSetAttribute(gates_ih_kernel, cudaFuncAttributeMaxDynamicSharedMemorySize, SMEMg);

    __nv_bfloat16 *wah, *wal, *wihh, *wihl, *whhh, *whhl;
    cudaGetSymbolAddress((void**)&wah,  g_Wah);
    cudaGetSymbolAddress((void**)&wal,  g_Wal);
    cudaGetSymbolAddress((void**)&wihh, g_Wihh);
    cudaGetSymbolAddress((void**)&wihl, g_Wihl);
    cudaGetSymbolAddress((void**)&whhh, g_Whhh);
    cudaGetSymbolAddress((void**)&whhl, g_Whhl);

    split_reorder_kernel<<<4096, 256>>>(W_ih, wihh, wihl, KV, Gg*KV);
    split_reorder_kernel<<<4096, 256>>>(W_hh, whhh, whhl, Hh, Gg*Hh);
    split_kernel<<<1024, 256>>>(W1, wah,           wal,           Ll*Hh);
    split_kernel<<<1024, 256>>>(W2, wah + Ll*Hh,   wal + Ll*Hh,   Ll*Hh);
    split_kernel<<<1024, 256>>>(W3, wah + 2*Ll*Hh, wal + 2*Ll*Hh, Ll*Hh);
    bias_prep_kernel<<<16, 256>>>(b_ih, b_hh, b1, b2, b3);
    init_kernel<<<(Bb*Hh + 255)/256, 256>>>(h0, c0);

    for (int t = 0; t < Tt; t++) {
        fusedA_kernel<<<152, 128, SMEMg>>>();              // logits + gates_hh (one wave)
        attnv_kernel<<<512, 384>>>(x);                     // softmax + value gather, D-split
        gates_ih_kernel<<<128, 128, SMEMg>>>(out, t);      // ih GEMM + LSTM epilogue
    }
}

// round 11
// speedup vs baseline: 1.3875x; 1.2202x over previous
#include <cuda_runtime.h>
#include <cuda_bf16.h>
#include <cuda_fp16.h>
#include <mma.h>
#include <cstdint>
#include <math.h>

using namespace nvcuda;

#define Bb 256
#define Ll 256
#define Dd 768
#define Hh 1024
#define Tt 32
#define KV (3*Dd)   // 2304
#define Gg (4*Hh)   // 4096
#define NL (3*Ll)   // 768
#define KCH 64      // K elems per smem chunk
#define LDS 72      // padded smem stride (elems), 144 B

// GEMM tile: 64x128 CTA, 128 threads (4 warps 2x2), warp tile 32x64 (FM=2, FN=4)
#define BMg 64
#define BNg 128
#define SSg ((2*BMg + 2*BNg) * LDS * 2)     // 55296 B per stage
#define AOFFg (BMg * LDS * 2)                // 9216
#define BOFFg (2 * BMg * LDS * 2)            // 18432
#define BLOFFg (BOFFg + BNg * LDS * 2)       // 36864
#define SMEMg (2 * SSg)                      // 110592

// ======================= device scratch =======================
__device__ float g_c[Bb*Hh];
__device__ float g_att0[Bb*NL], g_att1[Bb*NL];     // logits split-K partials
__device__ float g_gates0[Bb*Gg], g_gates1[Bb*Gg]; // hh split-K partials (gate-interleaved)
__device__ float g_ih0[Bb*Gg], g_ih1[Bb*Gg];       // ih split-K partials (gate-interleaved)
__device__ float g_biasG[Gg];             // reordered: [unit*4+gate]
__device__ float g_biasA[NL];
__device__ __align__(16) __half g_xh[Bb*Ll*Dd];    // x in fp16
__device__ __align__(16) __nv_bfloat16 g_hh_[Bb*Hh], g_hl_[Bb*Hh];
__device__ __align__(16) __nv_bfloat16 g_vh_[Bb*KV], g_vl_[Bb*KV];
__device__ __align__(16) __nv_bfloat16 g_Wah[NL*Hh],  g_Wal[NL*Hh];
__device__ __align__(16) __nv_bfloat16 g_Wihh[Gg*KV], g_Wihl[Gg*KV];   // rows reordered
__device__ __align__(16) __nv_bfloat16 g_Whhh[Gg*Hh], g_Whhl[Gg*Hh];   // rows reordered

__device__ __forceinline__ void split2(float a, __nv_bfloat16* hi, __nv_bfloat16* lo) {
    __nv_bfloat16 h = __float2bfloat16_rn(a);
    *hi = h;
    *lo = __float2bfloat16_rn(a - __bfloat162float(h));
}
__device__ __forceinline__ uint32_t smem_u32(const void* p) {
    uint32_t a;
    asm("{ .reg .u64 t; cvta.to.shared.u64 t, %1; cvt.u32.u64 %0, t; }" : "=r"(a) : "l"(p));
    return a;
}
__device__ __forceinline__ void cp16(uint32_t s, const void* g) {
    asm volatile("cp.async.cg.shared.global [%0], [%1], 16;" :: "r"(s), "l"(g));
}
#define CP_COMMIT() asm volatile("cp.async.commit_group;" ::: "memory")
#define CP_WAIT(n)  asm volatile("cp.async.wait_group %0;" :: "n"(n) : "memory")
__device__ __forceinline__ float sigmoidf_(float x) { return 1.0f / (1.0f + expf(-x)); }

// ======================= prep kernels =======================
__global__ void split_kernel(const float* __restrict__ src, __nv_bfloat16* __restrict__ hi,
                             __nv_bfloat16* __restrict__ lo, int n) {
    for (int i = blockIdx.x * blockDim.x + threadIdx.x; i < n; i += gridDim.x * blockDim.x)
        split2(src[i], &hi[i], &lo[i]);
}

__global__ void x2h_kernel(const float* __restrict__ x) {
    __half2* dst = (__half2*)g_xh;
    const float2* src = (const float2*)x;
    int n2 = Bb*Ll*Dd/2;
    for (int i = blockIdx.x * blockDim.x + threadIdx.x; i < n2; i += gridDim.x * blockDim.x) {
        float2 f = src[i];
        dst[i] = __floats2half2_rn(f.x, f.y);
    }
}

// split + gate-interleave row reorder: orig row r = gate*1024+unit -> r' = unit*4+gate
__global__ void split_reorder_kernel(const float* __restrict__ src, __nv_bfloat16* __restrict__ hi,
                                     __nv_bfloat16* __restrict__ lo, int K, int n) {
    for (int i = blockIdx.x * blockDim.x + threadIdx.x; i < n; i += gridDim.x * blockDim.x) {
        int r = i / K, k = i - r * K;
        int gate = r >> 10, unit = r & 1023;
        size_t dst = (size_t)(unit * 4 + gate) * K + k;
        split2(src[i], &hi[dst], &lo[dst]);
    }
}

__global__ void bias_prep_kernel(const float* __restrict__ b_ih, const float* __restrict__ b_hh,
                                 const float* __restrict__ b1, const float* __restrict__ b2,
                                 const float* __restrict__ b3) {
    int j = blockIdx.x * blockDim.x + threadIdx.x;
    if (j < Gg) {
        int gate = j >> 10, unit = j & 1023;
        g_biasG[unit * 4 + gate] = b_ih[j] + b_hh[j];
    }
    if (j < NL) g_biasA[j] = (j < Ll) ? b1[j] : (j < 2*Ll) ? b2[j - Ll] : b3[j - 2*Ll];
}

__global__ void init_kernel(const float* __restrict__ h0, const float* __restrict__ c0) {
    int i = blockIdx.x * blockDim.x + threadIdx.x;
    if (i < Bb*Hh) { split2(h0[i], &g_hh_[i], &g_hl_[i]); g_c[i] = c0[i]; }
}

// ======================= GEMM mainloop core (64x128 tile, 128 thr, warps 2x2) ===========
template <int NCH>
__device__ __forceinline__ void gemm_core(
    char* smem, uint32_t sb, int tid,
    const __nv_bfloat16* __restrict__ Ah, const __nv_bfloat16* __restrict__ Al,
    const __nv_bfloat16* __restrict__ Wh, const __nv_bfloat16* __restrict__ Wl,
    int K, int row0, int col0,
    wmma::fragment<wmma::accumulator, 16, 16, 16, float> (&acc)[2][4],
    int wm, int wn)
{
    auto load_chunk = [&](int kc, int s) {
        const int ka = kc * KCH;
        const uint32_t st = sb + s * SSg;
        #pragma unroll
        for (int it = 0; it < 4; it++) {                 // A: 64 rows
            int idx = tid + it * 128, r = idx >> 3, q = idx & 7;
            size_t src = (size_t)(row0 + r) * K + ka + q * 8;
            uint32_t off = r * (LDS*2) + q * 16;
            cp16(st + off, Ah + src);
            cp16(st + AOFFg + off, Al + src);
        }
        #pragma unroll
        for (int it = 0; it < 8; it++) {                 // B: 128 rows
            int idx = tid + it * 128, r = idx >> 3, q = idx & 7;
            size_t src = (size_t)(col0 + r) * K + ka + q * 8;
            uint32_t off = r * (LDS*2) + q * 16;
            cp16(st + BOFFg + off, Wh + src);
            cp16(st + BLOFFg + off, Wl + src);
        }
    };

    load_chunk(0, 0); CP_COMMIT();
    for (int kc = 0; kc < NCH; kc++) {
        if (kc + 1 < NCH) { load_chunk(kc + 1, (kc + 1) & 1); CP_COMMIT(); CP_WAIT(1); }
        else              { CP_WAIT(0); }
        __syncthreads();
        const char* st = smem + (kc & 1) * SSg;
        const __nv_bfloat16* pAh = (const __nv_bfloat16*)st;
        const __nv_bfloat16* pAl = (const __nv_bfloat16*)(st + AOFFg);
        const __nv_bfloat16* pBh = (const __nv_bfloat16*)(st + BOFFg);
        const __nv_bfloat16* pBl = (const __nv_bfloat16*)(st + BLOFFg);
        #pragma unroll
        for (int k16 = 0; k16 < KCH/16; k16++) {
            const int kk = k16 * 16;
            wmma::fragment<wmma::matrix_a, 16, 16, 16, __nv_bfloat16, wmma::row_major> ah[2], al[2];
            #pragma unroll
            for (int i = 0; i < 2; i++) {
                int rr = wm * 32 + i * 16;
                wmma::load_matrix_sync(ah[i], pAh + rr * LDS + kk, LDS);
                wmma::load_matrix_sync(al[i], pAl + rr * LDS + kk, LDS);
            }
            #pragma unroll
            for (int j = 0; j < 4; j++) {
                int cc = wn * 64 + j * 16;
                wmma::fragment<wmma::matrix_b, 16, 16, 16, __nv_bfloat16, wmma::col_major> bh, bl;
                wmma::load_matrix_sync(bh, pBh + cc * LDS + kk, LDS);
                wmma::load_matrix_sync(bl, pBl + cc * LDS + kk, LDS);
                #pragma unroll
                for (int i = 0; i < 2; i++) {
                    wmma::mma_sync(acc[i][j], ah[i], bh, acc[i][j]);
                    wmma::mma_sync(acc[i][j], ah[i], bl, acc[i][j]);
                    wmma::mma_sync(acc[i][j], al[i], bh, acc[i][j]);
                }
            }
        }
        __syncthreads();
    }
}

// ======================= fused launch A: logits + gates_hh, split-K 2-way ==========
// 304 CTAs x 128 thr: bid<48 -> logits (24 tiles x 2 K-halves); else hh (128 tiles x 2).
__global__ void __launch_bounds__(128) fusedA_kernel() {
    extern __shared__ __align__(16) char smem[];
    const uint32_t sb = smem_u32(smem);
    const int tid = threadIdx.x, wid = tid >> 5, wm = wid >> 1, wn = wid & 1;
    const int bid = blockIdx.x;

    int m_t, n_t, ko;
    const __nv_bfloat16 *Wh, *Wl;
    float* C;
    int Nt;
    if (bid < 48) {
        int half = bid >= 24, tt = half ? bid - 24 : bid;
        m_t = tt & 3; n_t = tt >> 2;            // 0..5
        ko = half * 512;
        Wh = g_Wah; Wl = g_Wal; C = half ? g_att1 : g_att0; Nt = NL;
    } else {
        int b2 = bid - 48;                       // 0..255
        int half = b2 >> 7, tt = b2 & 127;
        m_t = tt & 3; n_t = tt >> 2;             // 0..31
        ko = half * 512;
        Wh = g_Whhh; Wl = g_Whhl; C = half ? g_gates1 : g_gates0; Nt = Gg;
    }
    const int row0 = m_t * BMg, col0 = n_t * BNg;

    wmma::fragment<wmma::accumulator, 16, 16, 16, float> acc[2][4];
    #pragma unroll
    for (int i = 0; i < 2; i++) for (int j = 0; j < 4; j++) wmma::fill_fragment(acc[i][j], 0.0f);

    gemm_core<8>(smem, sb, tid, g_hh_ + ko, g_hl_ + ko, Wh + ko, Wl + ko,
                 Hh, row0, col0, acc, wm, wn);

    #pragma unroll
    for (int i = 0; i < 2; i++)
        #pragma unroll
        for (int j = 0; j < 4; j++) {
            int row = row0 + wm * 32 + i * 16;
            int col = col0 + wn * 64 + j * 16;
            wmma::store_matrix_sync(&C[(size_t)row * Nt + col], acc[i][j], Nt, wmma::mem_row_major);
        }
}

// ======================= gates_ih, split-K 2-way (A=v, K=2304 -> 2x1152) ===============
// 256 CTAs x 128 thr.
__global__ void __launch_bounds__(128) gates_ih_kernel() {
    extern __shared__ __align__(16) char smem[];
    const uint32_t sb = smem_u32(smem);
    const int tid = threadIdx.x, wid = tid >> 5, wm = wid >> 1, wn = wid & 1;
    const int bid = blockIdx.x;                 // 0..255
    const int half = bid >> 7, tt = bid & 127;
    const int m_t = tt & 3, n_t = tt >> 2;      // n_t 0..31
    const int row0 = m_t * BMg, col0 = n_t * BNg;
    const int ko = half * 1152;
    float* C = half ? g_ih1 : g_ih0;

    wmma::fragment<wmma::accumulator, 16, 16, 16, float> acc[2][4];
    #pragma unroll
    for (int i = 0; i < 2; i++) for (int j = 0; j < 4; j++) wmma::fill_fragment(acc[i][j], 0.0f);

    gemm_core<18>(smem, sb, tid, g_vh_ + ko, g_vl_ + ko, g_Wihh + ko, g_Wihl + ko,
                  KV, row0, col0, acc, wm, wn);

    #pragma unroll
    for (int i = 0; i < 2; i++)
        #pragma unroll
        for (int j = 0; j < 4; j++) {
            int row = row0 + wm * 32 + i * 16;
            int col = col0 + wn * 64 + j * 16;
            wmma::store_matrix_sync(&C[(size_t)row * Gg + col], acc[i][j], Gg, wmma::mem_row_major);
        }
}

// ======================= LSTM pointwise: sum 4 partials + bias =======================
__global__ void __launch_bounds__(256) lstm_kernel(float* __restrict__ out, int t_step) {
    int idx = blockIdx.x * blockDim.x + threadIdx.x;  // B*H
    int row = idx >> 10, u = idx & 1023;
    size_t go = (size_t)row * Gg + u * 4;
    float4 a0 = *(const float4*)&g_ih0[go];
    float4 a1 = *(const float4*)&g_ih1[go];
    float4 p0 = *(const float4*)&g_gates0[go];
    float4 p1 = *(const float4*)&g_gates1[go];
    float4 bv = *(const float4*)&g_biasG[u * 4];
    float ig = a0.x + a1.x + p0.x + p1.x + bv.x;
    float fg = a0.y + a1.y + p0.y + p1.y + bv.y;
    float gg = a0.z + a1.z + p0.z + p1.z + bv.z;
    float og = a0.w + a1.w + p0.w + p1.w + bv.w;
    float c = g_c[idx];
    float cn = sigmoidf_(fg) * c + sigmoidf_(ig) * tanhf(gg);
    float hn = sigmoidf_(og) * tanhf(cn);
    g_c[idx] = cn;
    split2(hn, &g_hh_[idx], &g_hl_[idx]);
    out[((size_t)row * Tt + t_step) * Hh + u] = hn;
}

// ======================= fused softmax + attention-value (fp16 x), D-split 2-way ========
// 512 CTAs x 384 thr: bid = b*2 + half. Each CTA handles D columns [half*384, +384).
__global__ void __launch_bounds__(384, 4) attnv_kernel() {
    const int bid = blockIdx.x;
    const int b = bid >> 1, half = bid & 1;
    const int tid = threadIdx.x;

    __shared__ float a[3][Ll];
    __shared__ float2 part[3][2][192];
    __shared__ float red[3][8];

    // --- softmax (threads 0..255), logits = att0 + att1 + bias ---
    float e[3], v[3];
    if (tid < 256) {
        #pragma unroll
        for (int h = 0; h < 3; h++)
            v[h] = g_att0[b * NL + h * 256 + tid] + g_att1[b * NL + h * 256 + tid]
                 + g_biasA[h * 256 + tid];
        int w8 = tid >> 5;
        #pragma unroll
        for (int h = 0; h < 3; h++) {
            float m = v[h];
            #pragma unroll
            for (int o = 16; o; o >>= 1) m = fmaxf(m, __shfl_xor_sync(0xffffffffu, m, o));
            if ((tid & 31) == 0) red[h][w8] = m;
        }
    }
    __syncthreads();
    if (tid < 256) {
        int w8 = tid >> 5;
        #pragma unroll
        for (int h = 0; h < 3; h++) {
            float mm = red[h][0];
            #pragma unroll
            for (int q = 1; q < 8; q++) mm = fmaxf(mm, red[h][q]);
            e[h] = expf(v[h] - mm);
        }
        __syncthreads();
        #pragma unroll
        for (int h = 0; h < 3; h++) {
            float s = e[h];
            #pragma unroll
            for (int o = 16; o; o >>= 1) s += __shfl_xor_sync(0xffffffffu, s, o);
            if ((tid & 31) == 0) red[h][w8] = s;
        }
    } else {
        __syncthreads();
    }
    __syncthreads();
    if (tid < 256) {
        #pragma unroll
        for (int h = 0; h < 3; h++) {
            float s = red[h][0];
            #pragma unroll
            for (int q = 1; q < 8; q++) s += red[h][q];
            a[h][tid] = e[h] / s;
        }
    }
    __syncthreads();

    // --- value gather over this CTA's D-half: 192 half2 cols, L split 2-way ---
    const int ty = tid / 192, tx = tid % 192;     // ty 0..1
    const __half2* xb2 = (const __half2*)g_xh + (size_t)b * Ll * (Dd/2) + half * 192;
    float2 s0 = {0,0}, s1 = {0,0}, s2 = {0,0};
    const int l0 = ty * 128;
    #pragma unroll 8
    for (int l = l0; l < l0 + 128; l++) {
        float w0 = a[0][l], w1 = a[1][l], w2 = a[2][l];
        float2 xv = __half22float2(xb2[(size_t)l * 384 + tx]);
        s0.x += w0*xv.x; s0.y += w0*xv.y;
        s1.x += w1*xv.x; s1.y += w1*xv.y;
        s2.x += w2*xv.x; s2.y += w2*xv.y;
    }
    part[0][ty][tx] = s0; part[1][ty][tx] = s1; part[2][ty][tx] = s2;
    __syncthreads();

    // reduce + split-write: 3 heads x 192 float2 = 576 items over 384 threads
    for (int sIdx = tid; sIdx < 576; sIdx += 384) {
        int h = sIdx / 192, c = sIdx % 192;
        float2 r0 = part[h][0][c], r1 = part[h][1][c];
        float rx = r0.x + r1.x, ry = r0.y + r1.y;
        size_t o = (size_t)b * KV + h * Dd + half * 384 + c * 2;
        split2(rx, &g_vh_[o],     &g_vl_[o]);
        split2(ry, &g_vh_[o + 1], &g_vl_[o + 1]);
    }
}

// ======================= driver (single stream, graph-safe) =======================
extern "C" void kernel_launch(void* const* d_in, const int* in_sizes, int n_in,
                              void* d_out, int out_size) {
    (void)in_sizes; (void)n_in; (void)out_size;
    const float* x    = (const float*)d_in[0];
    const float* h0   = (const float*)d_in[1];
    const float* c0   = (const float*)d_in[2];
    const float* W1   = (const float*)d_in[3];
    const float* b1   = (const float*)d_in[4];
    const float* W2   = (const float*)d_in[5];
    const float* b2   = (const float*)d_in[6];
    const float* W3   = (const float*)d_in[7];
    const float* b3   = (const float*)d_in[8];
    const float* W_ih = (const float*)d_in[9];
    const float* W_hh = (const float*)d_in[10];
    const float* b_ih = (const float*)d_in[11];
    const float* b_hh = (const float*)d_in[12];
    float* out = (float*)d_out;

    cudaFuncSetAttribute(fusedA_kernel,   cudaFuncAttributeMaxDynamicSharedMemorySize, SMEMg);
    cudaFuncSetAttribute(gates_ih_kernel, cudaFuncAttributeMaxDynamicSharedMemorySize, SMEMg);

    __nv_bfloat16 *wah, *wal, *wihh, *wihl, *whhh, *whhl;
    cudaGetSymbolAddress((void**)&wah,  g_Wah);
    cudaGetSymbolAddress((void**)&wal,  g_Wal);
    cudaGetSymbolAddress((void**)&wihh, g_Wihh);
    cudaGetSymbolAddress((void**)&wihl, g_Wihl);
    cudaGetSymbolAddress((void**)&whhh, g_Whhh);
    cudaGetSymbolAddress((void**)&whhl, g_Whhl);

    x2h_kernel<<<2048, 256>>>(x);
    split_reorder_kernel<<<4096, 256>>>(W_ih, wihh, wihl, KV, Gg*KV);
    split_reorder_kernel<<<4096, 256>>>(W_hh, whhh, whhl, Hh, Gg*Hh);
    split_kernel<<<1024, 256>>>(W1, wah,           wal,           Ll*Hh);
    split_kernel<<<1024, 256>>>(W2, wah + Ll*Hh,   wal + Ll*Hh,   Ll*Hh);
    split_kernel<<<1024, 256>>>(W3, wah + 2*Ll*Hh, wal + 2*Ll*Hh, Ll*Hh);
    bias_prep_kernel<<<16, 256>>>(b_ih, b_hh, b1, b2, b3);
    init_kernel<<<(Bb*Hh + 255)/256, 256>>>(h0, c0);

    for (int t = 0; t < Tt; t++) {
        fusedA_kernel<<<304, 128, SMEMg>>>();              // logits + gates_hh, split-K
        attnv_kernel<<<512, 384>>>();                      // softmax + fp16 value gather
        gates_ih_kernel<<<256, 128, SMEMg>>>();            // ih GEMM, split-K
        lstm_kernel<<<Bb*Hh/256, 256>>>(out, t);           // combine partials + LSTM
    }
}